// round 2
// baseline (speedup 1.0000x reference)
#include <cuda_runtime.h>
#include <cuda_fp16.h>
#include <cstdint>

// Problem constants (fixed by the dataset)
#define M_DIM 8192
#define K_DIM 4096
#define N_DIM 11008
#define NP    (N_DIM / 8)     // 1376 packed int32 per K row
#define BM 128
#define BN 128
#define BK 32

// Static __device__ scratch (allowed; no runtime allocation)
__device__ __half g_W[(size_t)K_DIM * N_DIM];   // 90 MB dequantized weights (fp16)
__device__ __half g_X[(size_t)M_DIM * K_DIM];   // 67 MB activations (fp32 -> fp16)

// ---------------------------------------------------------------------------
// Pass 0: convert x fp32 -> fp16 (harness upcast of original fp16 is lossless)
// ---------------------------------------------------------------------------
__global__ void convert_x_kernel(const float* __restrict__ x, int total) {
    int i = (blockIdx.x * blockDim.x + threadIdx.x) * 4;
    if (i >= total) return;
    float4 v = *reinterpret_cast<const float4*>(x + i);
    __half h[4];
    h[0] = __float2half(v.x); h[1] = __float2half(v.y);
    h[2] = __float2half(v.z); h[3] = __float2half(v.w);
    *reinterpret_cast<uint2*>(&g_X[i]) = *reinterpret_cast<uint2*>(h);
}

// ---------------------------------------------------------------------------
// Pass 1: dequantize AWQ int4 -> fp16 into g_W[k][n]
// One thread per packed int32 (8 nibbles, little-endian within int32).
// ---------------------------------------------------------------------------
__global__ void dequant_kernel(const int* __restrict__ qweight,
                               const int* __restrict__ qzeros,
                               const float* __restrict__ scales) {
    int idx = blockIdx.x * blockDim.x + threadIdx.x;
    if (idx >= K_DIM * NP) return;
    int k = idx / NP;
    int c = idx - k * NP;
    int g = k >> 7;  // k / 128 (groups = 32)

    uint32_t w = (uint32_t)qweight[idx];
    uint32_t z = (uint32_t)qzeros[g * NP + c];

    // 8 contiguous fp32 scales (32B aligned)
    const float* s = scales + (size_t)g * N_DIM + c * 8;
    float4 s0 = *reinterpret_cast<const float4*>(s);
    float4 s1 = *reinterpret_cast<const float4*>(s + 4);
    float sv[8] = {s0.x, s0.y, s0.z, s0.w, s1.x, s1.y, s1.z, s1.w};

    __half outv[8];
#pragma unroll
    for (int j = 0; j < 8; j++) {
        float wi = (float)((w >> (4 * j)) & 15u);
        float zi = (float)((z >> (4 * j)) & 15u);
        outv[j] = __float2half((wi - zi) * sv[j]);
    }
    *reinterpret_cast<uint4*>(&g_W[(size_t)k * N_DIM + c * 8]) =
        *reinterpret_cast<uint4*>(outv);
}

// ---------------------------------------------------------------------------
// Pass 2: fp16 GEMM  Out[M][N] = g_X[M][K] * g_W[K][N], fp32 output.
// 128x128x32 CTA tile, 8 warps (2x4), warp tile 64x32, mma.sync m16n8k16,
// cp.async double-buffered pipeline, fp32 accumulation.
// ---------------------------------------------------------------------------
__device__ __forceinline__ void cp_async16(void* smem, const void* gmem) {
    uint32_t s = (uint32_t)__cvta_generic_to_shared(smem);
    asm volatile("cp.async.cg.shared.global [%0], [%1], 16;\n"
                 :: "r"(s), "l"(gmem) : "memory");
}

__global__ __launch_bounds__(256, 2)
void gemm_kernel(float* __restrict__ Out) {
    // Padded strides keep ldmatrix phases conflict-free:
    // A row = 40 halves = 5*16B (odd #16B) ; B row = 136 halves = 17*16B (odd)
    __shared__ __half As[2][BM][40];
    __shared__ __half Bs[2][BK][136];

    const int tid  = threadIdx.x;
    const int warp = tid >> 5;
    const int lane = tid & 31;
    const int wm = (warp & 1) * 64;   // warp m-offset in CTA tile
    const int wn = (warp >> 1) * 32;  // warp n-offset in CTA tile

    const int bm = blockIdx.y * BM;
    const int bn = blockIdx.x * BN;

    float acc[4][4][4];
#pragma unroll
    for (int i = 0; i < 4; i++)
#pragma unroll
        for (int j = 0; j < 4; j++)
#pragma unroll
            for (int r = 0; r < 4; r++) acc[i][j][r] = 0.f;

    // Global->shared mapping (16B cp.async, fully coalesced)
    const int a_row = tid >> 2;          // 0..63 (+64 second iter)
    const int a_col = (tid & 3) * 8;     // 0/8/16/24
    const int b_row = tid >> 4;          // 0..15 (+16 second iter)
    const int b_col = (tid & 15) * 8;    // 0..120

    auto load_tile = [&](int kt, int bufi) {
        const int k0 = kt * BK;
#pragma unroll
        for (int it = 0; it < 2; it++) {
            int r = a_row + it * 64;
            cp_async16(&As[bufi][r][a_col],
                       g_X + (size_t)(bm + r) * K_DIM + k0 + a_col);
        }
#pragma unroll
        for (int it = 0; it < 2; it++) {
            int r = b_row + it * 16;
            cp_async16(&Bs[bufi][r][b_col],
                       g_W + (size_t)(k0 + r) * N_DIM + bn + b_col);
        }
    };

    const int KT = K_DIM / BK;  // 128
    int buf = 0;
    load_tile(0, 0);
    asm volatile("cp.async.commit_group;\n" ::: "memory");

    for (int kt = 0; kt < KT; kt++) {
        if (kt + 1 < KT) load_tile(kt + 1, buf ^ 1);
        asm volatile("cp.async.commit_group;\n" ::: "memory");
        asm volatile("cp.async.wait_group 1;\n" ::: "memory");
        __syncthreads();

#pragma unroll
        for (int kk = 0; kk < 2; kk++) {  // two k16 chunks per BK=32
            uint32_t a[4][4];
#pragma unroll
            for (int i = 0; i < 4; i++) {
                uint32_t addr = (uint32_t)__cvta_generic_to_shared(
                    &As[buf][wm + i * 16 + (lane & 15)][kk * 16 + ((lane >> 4) << 3)]);
                asm volatile(
                    "ldmatrix.sync.aligned.m8n8.x4.shared.b16 {%0,%1,%2,%3}, [%4];\n"
                    : "=r"(a[i][0]), "=r"(a[i][1]), "=r"(a[i][2]), "=r"(a[i][3])
                    : "r"(addr));
            }
            uint32_t b[4][2];
#pragma unroll
            for (int jj = 0; jj < 2; jj++) {
                uint32_t addr = (uint32_t)__cvta_generic_to_shared(
                    &Bs[buf][kk * 16 + (lane & 15)][wn + jj * 16 + ((lane >> 4) << 3)]);
                uint32_t r0, r1, r2, r3;
                asm volatile(
                    "ldmatrix.sync.aligned.m8n8.x4.trans.shared.b16 {%0,%1,%2,%3}, [%4];\n"
                    : "=r"(r0), "=r"(r1), "=r"(r2), "=r"(r3)
                    : "r"(addr));
                b[jj * 2][0] = r0;     b[jj * 2][1] = r1;
                b[jj * 2 + 1][0] = r2; b[jj * 2 + 1][1] = r3;
            }
#pragma unroll
            for (int i = 0; i < 4; i++)
#pragma unroll
                for (int j = 0; j < 4; j++) {
                    asm volatile(
                        "mma.sync.aligned.m16n8k16.row.col.f32.f16.f16.f32 "
                        "{%0,%1,%2,%3}, {%4,%5,%6,%7}, {%8,%9}, {%0,%1,%2,%3};\n"
                        : "+f"(acc[i][j][0]), "+f"(acc[i][j][1]),
                          "+f"(acc[i][j][2]), "+f"(acc[i][j][3])
                        : "r"(a[i][0]), "r"(a[i][1]), "r"(a[i][2]), "r"(a[i][3]),
                          "r"(b[j][0]), "r"(b[j][1]));
                }
        }
        __syncthreads();
        buf ^= 1;
    }

    // Epilogue: fp32 output, float2 stores (8B aligned: col % 2 == 0)
#pragma unroll
    for (int i = 0; i < 4; i++) {
        int row = bm + wm + i * 16 + (lane >> 2);
#pragma unroll
        for (int j = 0; j < 4; j++) {
            int col = bn + wn + j * 8 + (lane & 3) * 2;
            float2 v0 = make_float2(acc[i][j][0], acc[i][j][1]);
            float2 v1 = make_float2(acc[i][j][2], acc[i][j][3]);
            *reinterpret_cast<float2*>(&Out[(size_t)row * N_DIM + col]) = v0;
            *reinterpret_cast<float2*>(&Out[(size_t)(row + 8) * N_DIM + col]) = v1;
        }
    }
}

// ---------------------------------------------------------------------------
extern "C" void kernel_launch(void* const* d_in, const int* in_sizes, int n_in,
                              void* d_out, int out_size) {
    const float* x  = (const float*)d_in[0];   // [4,2048,4096] fp32 (upcast fp16)
    const int*   qw = (const int*)d_in[1];     // [4096,1376]  int32
    const int*   qz = (const int*)d_in[2];     // [32,1376]    int32
    const float* sc = (const float*)d_in[3];   // [32,11008]   fp32 (upcast fp16)
    float* out = (float*)d_out;                // [4,2048,11008] fp32

    const int x_total = in_sizes[0];           // 33,554,432

    convert_x_kernel<<<(x_total / 4 + 255) / 256, 256>>>(x, x_total);

    int total = K_DIM * NP;
    dequant_kernel<<<(total + 255) / 256, 256>>>(qw, qz, sc);

    dim3 grid(N_DIM / BN, M_DIM / BM);         // (86, 64)
    gemm_kernel<<<grid, 256>>>(out);
}

// round 4
// speedup vs baseline: 2.1378x; 2.1378x over previous
#include <cuda_runtime.h>
#include <cuda_fp16.h>
#include <cstdint>

// Problem constants
#define M_DIM 8192
#define K_DIM 4096
#define N_DIM 11008
#define NP    (N_DIM / 8)

// tcgen05 GEMM tiling
#define BM 128
#define BN 256
#define BK 64
#define STAGE_A_BYTES (BM * BK * 2)
#define STAGE_B_BYTES (BN * BK * 2)
#define STAGE_BYTES   (STAGE_A_BYTES + STAGE_B_BYTES)   // 49152
#define SMEM_STAGES   (4 * STAGE_BYTES)                 // 196608
#define SMEM_TOTAL    (SMEM_STAGES + 1024 + 128)

// Fallback GEMM tiling (mma.sync): 128x128x32, 3 stages
#define FB_STRIDE 40
#define FB_STAGE_HALFS (128 * FB_STRIDE)
#define FB_SMEM_BYTES (3 * 2 * FB_STAGE_HALFS * 2)      // 61440

// Static device scratch
__device__ __half g_Wt[(size_t)N_DIM * K_DIM];  // W transposed [N][K], fp16
__device__ __half g_X [(size_t)M_DIM * K_DIM];  // activations fp16
__device__ int    g_done;                       // tcgen05 path completion flag

// ---------------------------------------------------------------------------
// Common PTX helpers (compute_103-safe)
// ---------------------------------------------------------------------------
__device__ __forceinline__ void cp_async16(uint32_t smem, const void* gmem) {
    asm volatile("cp.async.cg.shared.global [%0], [%1], 16;\n"
                 :: "r"(smem), "l"(gmem) : "memory");
}

__global__ void reset_flag_kernel() { g_done = 0; }

// ---------------------------------------------------------------------------
// Pass 0: x fp32 -> fp16 (lossless)
// ---------------------------------------------------------------------------
__global__ void convert_x_kernel(const float* __restrict__ x, int total) {
    int i = (blockIdx.x * blockDim.x + threadIdx.x) * 4;
    if (i >= total) return;
    float4 v = *reinterpret_cast<const float4*>(x + i);
    __half h[4];
    h[0] = __float2half(v.x); h[1] = __float2half(v.y);
    h[2] = __float2half(v.z); h[3] = __float2half(v.w);
    *reinterpret_cast<uint2*>(&g_X[i]) = *reinterpret_cast<uint2*>(h);
}

// ---------------------------------------------------------------------------
// Pass 1: dequant AWQ int4 -> fp16 transposed g_Wt[n][k] (smem transpose)
// ---------------------------------------------------------------------------
__global__ __launch_bounds__(256)
void dequant_t_kernel(const int* __restrict__ qweight,
                      const int* __restrict__ qzeros,
                      const float* __restrict__ scales) {
    __shared__ __half s[256][64];
    const int k0 = blockIdx.x * 64;
    const int n0 = blockIdx.y * 256;
    const int g  = k0 >> 7;
    const int c0 = n0 >> 3;
    const int tid = threadIdx.x;

#pragma unroll
    for (int i = 0; i < 8; i++) {
        int lin = tid + 256 * i;
        int cl  = lin & 31;
        int kl  = lin >> 5;
        uint32_t w = (uint32_t)qweight[(size_t)(k0 + kl) * NP + c0 + cl];
        uint32_t z = (uint32_t)qzeros[(size_t)g * NP + c0 + cl];
        const float* sp = scales + (size_t)g * N_DIM + n0 + cl * 8;
#pragma unroll
        for (int j = 0; j < 8; j++) {
            float wi = (float)((w >> (4 * j)) & 15u);
            float zi = (float)((z >> (4 * j)) & 15u);
            __half v = __float2half((wi - zi) * sp[j]);
            int nl = cl * 8 + j;
            int phys16 = (kl >> 3) ^ ((nl >> 3) & 7);
            s[nl][(phys16 << 3) | (kl & 7)] = v;
        }
    }
    __syncthreads();
#pragma unroll
    for (int i = 0; i < 8; i++) {
        int idx = tid + 256 * i;
        int r = idx >> 3, q = idx & 7;
        int phys16 = q ^ ((r >> 3) & 7);
        uint4 v = *reinterpret_cast<uint4*>(&s[r][phys16 << 3]);
        *reinterpret_cast<uint4*>(&g_Wt[(size_t)(n0 + r) * K_DIM + k0 + q * 8]) = v;
    }
}

// ---------------------------------------------------------------------------
// tcgen05 GEMM (only compiled when the device pass targets sm_103a)
// ---------------------------------------------------------------------------
#if defined(__CUDA_ARCH__) && (defined(__CUDA_ARCH_FEAT_SM103_ALL) || defined(__CUDA_ARCH_FEAT_SM100_ALL) || defined(__CUDA_ARCH_FEAT_SM101_ALL))
#define TC_LIVE 1
#endif

#ifdef TC_LIVE
__device__ __forceinline__ uint32_t elect_one() {
    uint32_t p;
    asm volatile("{\n\t.reg .pred P;\n\telect.sync _|P, 0xFFFFFFFF;\n\t"
                 "selp.b32 %0, 1, 0, P;\n\t}" : "=r"(p));
    return p;
}
__device__ __forceinline__ void mbar_init(uint32_t a, uint32_t cnt) {
    asm volatile("mbarrier.init.shared.b64 [%0], %1;" :: "r"(a), "r"(cnt) : "memory");
}
__device__ __forceinline__ void mbar_wait(uint32_t a, uint32_t parity) {
    asm volatile("{\n\t.reg .pred P;\n\tLW%=:\n\t"
                 "mbarrier.try_wait.parity.acquire.cta.shared::cta.b64 P, [%0], %1;\n\t"
                 "@!P bra LW%=;\n\t}" :: "r"(a), "r"(parity) : "memory");
}
__device__ __forceinline__ void tc_commit(uint32_t mbar) {
    asm volatile("tcgen05.commit.cta_group::1.mbarrier::arrive::one.shared::cluster.b64 [%0];"
                 :: "r"(mbar) : "memory");
}
__device__ __forceinline__ void mma_f16_ss(uint32_t d, uint64_t ad, uint64_t bd,
                                           uint32_t idesc, uint32_t en) {
    asm volatile("{\n\t.reg .pred p;\n\tsetp.ne.u32 p, %4, 0;\n\t"
                 "tcgen05.mma.cta_group::1.kind::f16 [%0], %1, %2, %3, {%5,%5,%5,%5}, p;\n\t}"
                 :: "r"(d), "l"(ad), "l"(bd), "r"(idesc), "r"(en), "r"(0u) : "memory");
}
__device__ __forceinline__ uint64_t make_desc(uint32_t smem_addr) {
    return ((uint64_t)2 << 61) | ((uint64_t)1 << 46) | ((uint64_t)64 << 32) |
           ((uint64_t)1 << 16) | (((uint64_t)(smem_addr >> 4)) & 0x3FFF);
}
__device__ __forceinline__ void ldtm_x32(uint32_t* r, uint32_t tmem) {
    asm volatile(
        "tcgen05.ld.sync.aligned.32x32b.x32.b32 "
        "{%0,%1,%2,%3,%4,%5,%6,%7,%8,%9,%10,%11,%12,%13,%14,%15,"
        "%16,%17,%18,%19,%20,%21,%22,%23,%24,%25,%26,%27,%28,%29,%30,%31}, [%32];"
        : "=r"(r[0]),"=r"(r[1]),"=r"(r[2]),"=r"(r[3]),"=r"(r[4]),"=r"(r[5]),"=r"(r[6]),"=r"(r[7]),
          "=r"(r[8]),"=r"(r[9]),"=r"(r[10]),"=r"(r[11]),"=r"(r[12]),"=r"(r[13]),"=r"(r[14]),"=r"(r[15]),
          "=r"(r[16]),"=r"(r[17]),"=r"(r[18]),"=r"(r[19]),"=r"(r[20]),"=r"(r[21]),"=r"(r[22]),"=r"(r[23]),
          "=r"(r[24]),"=r"(r[25]),"=r"(r[26]),"=r"(r[27]),"=r"(r[28]),"=r"(r[29]),"=r"(r[30]),"=r"(r[31])
        : "r"(tmem));
}
#endif  // TC_LIVE

__global__ __launch_bounds__(256, 1)
void gemm_tc_kernel(float* __restrict__ Out) {
#ifdef TC_LIVE
    if (threadIdx.x == 0) g_done = 1;

    extern __shared__ char smem_raw[];
    char* smem = (char*)(((uintptr_t)smem_raw + 1023) & ~(uintptr_t)1023);
    const uint32_t sbase = (uint32_t)__cvta_generic_to_shared(smem);
    const uint32_t mbarb = sbase + SMEM_STAGES;

    const int tid  = threadIdx.x;
    const int wid  = tid >> 5;
    const int lane = tid & 31;
    const int bm = blockIdx.x * BM;
    const int bn = blockIdx.y * BN;

    if (tid == 0) {
#pragma unroll
        for (int i = 0; i < 5; i++) mbar_init(mbarb + 8 * i, 1);
    }
    if (wid == 0) {
        asm volatile("tcgen05.alloc.cta_group::1.sync.aligned.shared::cta.b32 [%0], %1;"
                     :: "r"(mbarb + 40), "r"(256) : "memory");
        asm volatile("tcgen05.relinquish_alloc_permit.cta_group::1.sync.aligned;");
    }
    __syncthreads();
    uint32_t tmem;
    asm volatile("ld.shared.b32 %0, [%1];" : "=r"(tmem) : "r"(mbarb + 40));

    auto load_chunk = [&](int kt, int s) {
        uint32_t a_s = sbase + s * STAGE_BYTES;
        uint32_t b_s = a_s + STAGE_A_BYTES;
        const __half* Ag = g_X  + (size_t)bm * K_DIM + kt * BK;
        const __half* Bg = g_Wt + (size_t)bn * K_DIM + kt * BK;
#pragma unroll
        for (int i = 0; i < 4; i++) {
            int idx = tid + 256 * i;
            int row = idx >> 3, c16 = idx & 7;
            cp_async16(a_s + row * 128 + ((c16 ^ (row & 7)) << 4),
                       Ag + (size_t)row * K_DIM + c16 * 8);
        }
#pragma unroll
        for (int i = 0; i < 8; i++) {
            int idx = tid + 256 * i;
            int row = idx >> 3, c16 = idx & 7;
            cp_async16(b_s + row * 128 + ((c16 ^ (row & 7)) << 4),
                       Bg + (size_t)row * K_DIM + c16 * 8);
        }
    };

    const uint32_t idesc = (8u << 24) | (16u << 17) | (1u << 4);  // M=128, N=128, f16->f32
    const int KT = K_DIM / BK;  // 64

#pragma unroll
    for (int kt = 0; kt < 3; kt++) {
        load_chunk(kt, kt);
        asm volatile("cp.async.commit_group;" ::: "memory");
    }

    for (int kt = 0; kt < KT; kt++) {
        const int s = kt & 3;
        if (kt >= 1)
            mbar_wait(mbarb + 8 * ((kt + 3) & 3), ((kt - 1) >> 2) & 1);
        if (kt + 3 < KT) load_chunk(kt + 3, (kt + 3) & 3);
        asm volatile("cp.async.commit_group;" ::: "memory");
        asm volatile("cp.async.wait_group 3;" ::: "memory");
        __syncthreads();

        if (wid == 0) {
            asm volatile("fence.proxy.async.shared::cta;" ::: "memory");
            if (elect_one()) {
                uint32_t a_s = sbase + s * STAGE_BYTES;
                uint32_t b_s = a_s + STAGE_A_BYTES;
                uint64_t ad  = make_desc(a_s);
                uint64_t bd0 = make_desc(b_s);
                uint64_t bd1 = make_desc(b_s + 16384);
#pragma unroll
                for (int ks = 0; ks < 4; ks++) {
                    uint32_t en = (kt > 0 || ks > 0) ? 1u : 0u;
                    mma_f16_ss(tmem,       ad + ks * 2, bd0 + ks * 2, idesc, en);
                    mma_f16_ss(tmem + 128, ad + ks * 2, bd1 + ks * 2, idesc, en);
                }
                tc_commit(mbarb + 8 * s);
            }
        }
    }

    if (wid == 0 && elect_one()) tc_commit(mbarb + 32);
    mbar_wait(mbarb + 32, 0);
    asm volatile("tcgen05.fence::after_thread_sync;" ::: "memory");

    {
        const int row = bm + (wid & 3) * 32 + lane;
        const int cb  = bn + (wid >> 2) * 128;
        float* dst = Out + (size_t)row * N_DIM + cb;
        const uint32_t tm = tmem + (wid >> 2) * 128;
#pragma unroll
        for (int b = 0; b < 4; b++) {
            uint32_t v[32];
            ldtm_x32(v, tm + b * 32);
            asm volatile("tcgen05.wait::ld.sync.aligned;" ::: "memory");
#pragma unroll
            for (int i = 0; i < 8; i++) {
                float4 f;
                f.x = __uint_as_float(v[4 * i + 0]);
                f.y = __uint_as_float(v[4 * i + 1]);
                f.z = __uint_as_float(v[4 * i + 2]);
                f.w = __uint_as_float(v[4 * i + 3]);
                *reinterpret_cast<float4*>(dst + b * 32 + i * 4) = f;
            }
        }
    }
    __syncthreads();
    if (wid == 0) {
        asm volatile("tcgen05.dealloc.cta_group::1.sync.aligned.b32 %0, %1;"
                     :: "r"(tmem), "r"(256));
    }
#endif  // TC_LIVE
}

// ---------------------------------------------------------------------------
// Fallback GEMM (mma.sync m16n8k16). Runs only if tcgen05 path was stubbed.
// 128x128x32 tile, 8 warps (2x4), 3-stage cp.async, one sync per iter.
// B consumed from g_Wt[N][K] via non-trans ldmatrix.
// ---------------------------------------------------------------------------
__global__ __launch_bounds__(256, 2)
void gemm_fb_kernel(float* __restrict__ Out) {
    if (*(volatile int*)&g_done) return;

    extern __shared__ __half fsm[];
    __half (*As)[128][FB_STRIDE] = (__half(*)[128][FB_STRIDE])fsm;
    __half (*Bs)[128][FB_STRIDE] = (__half(*)[128][FB_STRIDE])(fsm + 3 * FB_STAGE_HALFS);

    const int tid  = threadIdx.x;
    const int warp = tid >> 5;
    const int lane = tid & 31;
    const int wm = (warp & 1) * 64;
    const int wn = (warp >> 1) * 32;
    const int bm = blockIdx.y * 128;
    const int bn = blockIdx.x * 128;

    float acc[4][4][4];
#pragma unroll
    for (int i = 0; i < 4; i++)
#pragma unroll
        for (int j = 0; j < 4; j++)
#pragma unroll
            for (int r = 0; r < 4; r++) acc[i][j][r] = 0.f;

    const int l_row = tid >> 2;          // 0..63 (+64)
    const int l_col = (tid & 3) * 8;

    auto load = [&](int kt, int s) {
        const int k0 = kt * 32;
#pragma unroll
        for (int it = 0; it < 2; it++) {
            int r = l_row + it * 64;
            cp_async16((uint32_t)__cvta_generic_to_shared(&As[s][r][l_col]),
                       g_X + (size_t)(bm + r) * K_DIM + k0 + l_col);
        }
#pragma unroll
        for (int it = 0; it < 2; it++) {
            int r = l_row + it * 64;
            cp_async16((uint32_t)__cvta_generic_to_shared(&Bs[s][r][l_col]),
                       g_Wt + (size_t)(bn + r) * K_DIM + k0 + l_col);
        }
    };

    const int KT = K_DIM / 32;  // 128
    load(0, 0);
    asm volatile("cp.async.commit_group;" ::: "memory");
    load(1, 1);
    asm volatile("cp.async.commit_group;" ::: "memory");

    for (int kt = 0; kt < KT; kt++) {
        const int s = kt % 3;
        asm volatile("cp.async.wait_group 1;" ::: "memory");
        __syncthreads();
        if (kt + 2 < KT) load(kt + 2, (kt + 2) % 3);
        asm volatile("cp.async.commit_group;" ::: "memory");

#pragma unroll
        for (int kk = 0; kk < 2; kk++) {
            uint32_t a[4][4];
#pragma unroll
            for (int i = 0; i < 4; i++) {
                uint32_t addr = (uint32_t)__cvta_generic_to_shared(
                    &As[s][wm + i * 16 + (lane & 15)][kk * 16 + ((lane >> 4) << 3)]);
                asm volatile(
                    "ldmatrix.sync.aligned.m8n8.x4.shared.b16 {%0,%1,%2,%3}, [%4];\n"
                    : "=r"(a[i][0]), "=r"(a[i][1]), "=r"(a[i][2]), "=r"(a[i][3])
                    : "r"(addr));
            }
            uint32_t b[4][2];
#pragma unroll
            for (int jj = 0; jj < 2; jj++) {
                int grp = lane >> 3;   // 0..3
                uint32_t addr = (uint32_t)__cvta_generic_to_shared(
                    &Bs[s][wn + jj * 16 + (grp >> 1) * 8 + (lane & 7)]
                         [kk * 16 + (grp & 1) * 8]);
                uint32_t r0, r1, r2, r3;
                asm volatile(
                    "ldmatrix.sync.aligned.m8n8.x4.shared.b16 {%0,%1,%2,%3}, [%4];\n"
                    : "=r"(r0), "=r"(r1), "=r"(r2), "=r"(r3)
                    : "r"(addr));
                b[jj * 2][0] = r0;     b[jj * 2][1] = r1;
                b[jj * 2 + 1][0] = r2; b[jj * 2 + 1][1] = r3;
            }
#pragma unroll
            for (int i = 0; i < 4; i++)
#pragma unroll
                for (int j = 0; j < 4; j++) {
                    asm volatile(
                        "mma.sync.aligned.m16n8k16.row.col.f32.f16.f16.f32 "
                        "{%0,%1,%2,%3}, {%4,%5,%6,%7}, {%8,%9}, {%0,%1,%2,%3};\n"
                        : "+f"(acc[i][j][0]), "+f"(acc[i][j][1]),
                          "+f"(acc[i][j][2]), "+f"(acc[i][j][3])
                        : "r"(a[i][0]), "r"(a[i][1]), "r"(a[i][2]), "r"(a[i][3]),
                          "r"(b[j][0]), "r"(b[j][1]));
                }
        }
    }

#pragma unroll
    for (int i = 0; i < 4; i++) {
        int row = bm + wm + i * 16 + (lane >> 2);
#pragma unroll
        for (int j = 0; j < 4; j++) {
            int col = bn + wn + j * 8 + (lane & 3) * 2;
            *reinterpret_cast<float2*>(&Out[(size_t)row * N_DIM + col]) =
                make_float2(acc[i][j][0], acc[i][j][1]);
            *reinterpret_cast<float2*>(&Out[(size_t)(row + 8) * N_DIM + col]) =
                make_float2(acc[i][j][2], acc[i][j][3]);
        }
    }
}

// ---------------------------------------------------------------------------
extern "C" void kernel_launch(void* const* d_in, const int* in_sizes, int n_in,
                              void* d_out, int out_size) {
    const float* x  = (const float*)d_in[0];
    const int*   qw = (const int*)d_in[1];
    const int*   qz = (const int*)d_in[2];
    const float* sc = (const float*)d_in[3];
    float* out = (float*)d_out;

    cudaFuncSetAttribute(gemm_tc_kernel, cudaFuncAttributeMaxDynamicSharedMemorySize,
                         SMEM_TOTAL);
    cudaFuncSetAttribute(gemm_fb_kernel, cudaFuncAttributeMaxDynamicSharedMemorySize,
                         FB_SMEM_BYTES);

    reset_flag_kernel<<<1, 1>>>();

    const int x_total = in_sizes[0];
    convert_x_kernel<<<(x_total / 4 + 255) / 256, 256>>>(x, x_total);

    dim3 dq_grid(K_DIM / 64, N_DIM / 256);
    dequant_t_kernel<<<dq_grid, 256>>>(qw, qz, sc);

    dim3 tc_grid(M_DIM / BM, N_DIM / BN);       // (64, 43)
    gemm_tc_kernel<<<tc_grid, 256, SMEM_TOTAL>>>(out);

    dim3 fb_grid(N_DIM / 128, M_DIM / 128);     // (86, 64)
    gemm_fb_kernel<<<fb_grid, 256, FB_SMEM_BYTES>>>(out);
}

// round 5
// speedup vs baseline: 2.7913x; 1.3057x over previous
#include <cuda_runtime.h>
#include <cuda_fp16.h>
#include <cstdint>

// Problem constants
#define M_DIM 8192
#define K_DIM 4096
#define N_DIM 11008
#define NP    (N_DIM / 8)

// tcgen05 GEMM tiling: CTA tile 256x256, BK=64, 3 stages
#define BM 256
#define BN 256
#define BK 64
#define STAGE_A_BYTES (BM * BK * 2)                     // 32768
#define STAGE_B_BYTES (BN * BK * 2)                     // 32768
#define STAGE_BYTES   (STAGE_A_BYTES + STAGE_B_BYTES)   // 65536
#define NSTAGES 3
#define SMEM_STAGES   (NSTAGES * STAGE_BYTES)           // 196608
#define SMEM_TOTAL    (SMEM_STAGES + 1024 + 128)

// Fallback GEMM tiling (mma.sync): 128x128x32, 3 stages
#define FB_STRIDE 40
#define FB_STAGE_HALFS (128 * FB_STRIDE)
#define FB_SMEM_BYTES (3 * 2 * FB_STAGE_HALFS * 2)      // 61440

// Static device scratch
__device__ __half g_Wt[(size_t)N_DIM * K_DIM];  // W transposed [N][K], fp16
__device__ __half g_X [(size_t)M_DIM * K_DIM];  // activations fp16
__device__ int    g_done;

// ---------------------------------------------------------------------------
__device__ __forceinline__ void cp_async16(uint32_t smem, const void* gmem) {
    asm volatile("cp.async.cg.shared.global [%0], [%1], 16;\n"
                 :: "r"(smem), "l"(gmem) : "memory");
}

__global__ void reset_flag_kernel() { g_done = 0; }

// ---------------------------------------------------------------------------
// Pass 0: x fp32 -> fp16 (lossless)
// ---------------------------------------------------------------------------
__global__ void convert_x_kernel(const float* __restrict__ x, int total) {
    int i = (blockIdx.x * blockDim.x + threadIdx.x) * 4;
    if (i >= total) return;
    float4 v = *reinterpret_cast<const float4*>(x + i);
    __half h[4];
    h[0] = __float2half(v.x); h[1] = __float2half(v.y);
    h[2] = __float2half(v.z); h[3] = __float2half(v.w);
    *reinterpret_cast<uint2*>(&g_X[i]) = *reinterpret_cast<uint2*>(h);
}

// ---------------------------------------------------------------------------
// Pass 1: dequant AWQ int4 -> fp16 transposed g_Wt[n][k] (smem transpose)
// ---------------------------------------------------------------------------
__global__ __launch_bounds__(256)
void dequant_t_kernel(const int* __restrict__ qweight,
                      const int* __restrict__ qzeros,
                      const float* __restrict__ scales) {
    __shared__ __half s[256][64];
    const int k0 = blockIdx.x * 64;
    const int n0 = blockIdx.y * 256;
    const int g  = k0 >> 7;
    const int c0 = n0 >> 3;
    const int tid = threadIdx.x;

#pragma unroll
    for (int i = 0; i < 8; i++) {
        int lin = tid + 256 * i;
        int cl  = lin & 31;
        int kl  = lin >> 5;
        uint32_t w = (uint32_t)qweight[(size_t)(k0 + kl) * NP + c0 + cl];
        uint32_t z = (uint32_t)qzeros[(size_t)g * NP + c0 + cl];
        const float* sp = scales + (size_t)g * N_DIM + n0 + cl * 8;
#pragma unroll
        for (int j = 0; j < 8; j++) {
            float wi = (float)((w >> (4 * j)) & 15u);
            float zi = (float)((z >> (4 * j)) & 15u);
            __half v = __float2half((wi - zi) * sp[j]);
            int nl = cl * 8 + j;
            int phys16 = (kl >> 3) ^ ((nl >> 3) & 7);
            s[nl][(phys16 << 3) | (kl & 7)] = v;
        }
    }
    __syncthreads();
#pragma unroll
    for (int i = 0; i < 8; i++) {
        int idx = tid + 256 * i;
        int r = idx >> 3, q = idx & 7;
        int phys16 = q ^ ((r >> 3) & 7);
        uint4 v = *reinterpret_cast<uint4*>(&s[r][phys16 << 3]);
        *reinterpret_cast<uint4*>(&g_Wt[(size_t)(n0 + r) * K_DIM + k0 + q * 8]) = v;
    }
}

// ---------------------------------------------------------------------------
// tcgen05 GEMM (device pass must target sm_103a / sm_100a family)
// ---------------------------------------------------------------------------
#if defined(__CUDA_ARCH__) && (defined(__CUDA_ARCH_FEAT_SM103_ALL) || defined(__CUDA_ARCH_FEAT_SM100_ALL) || defined(__CUDA_ARCH_FEAT_SM101_ALL))
#define TC_LIVE 1
#endif

#ifdef TC_LIVE
__device__ __forceinline__ uint32_t elect_one() {
    uint32_t p;
    asm volatile("{\n\t.reg .pred P;\n\telect.sync _|P, 0xFFFFFFFF;\n\t"
                 "selp.b32 %0, 1, 0, P;\n\t}" : "=r"(p));
    return p;
}
__device__ __forceinline__ void mbar_init(uint32_t a, uint32_t cnt) {
    asm volatile("mbarrier.init.shared.b64 [%0], %1;" :: "r"(a), "r"(cnt) : "memory");
}
__device__ __forceinline__ void mbar_wait(uint32_t a, uint32_t parity) {
    asm volatile("{\n\t.reg .pred P;\n\tLW%=:\n\t"
                 "mbarrier.try_wait.parity.acquire.cta.shared::cta.b64 P, [%0], %1;\n\t"
                 "@!P bra LW%=;\n\t}" :: "r"(a), "r"(parity) : "memory");
}
__device__ __forceinline__ void tc_commit(uint32_t mbar) {
    asm volatile("tcgen05.commit.cta_group::1.mbarrier::arrive::one.shared::cluster.b64 [%0];"
                 :: "r"(mbar) : "memory");
}
__device__ __forceinline__ void mma_f16_ss(uint32_t d, uint64_t ad, uint64_t bd,
                                           uint32_t idesc, uint32_t en) {
    asm volatile("{\n\t.reg .pred p;\n\tsetp.ne.u32 p, %4, 0;\n\t"
                 "tcgen05.mma.cta_group::1.kind::f16 [%0], %1, %2, %3, {%5,%5,%5,%5}, p;\n\t}"
                 :: "r"(d), "l"(ad), "l"(bd), "r"(idesc), "r"(en), "r"(0u) : "memory");
}
__device__ __forceinline__ uint64_t make_desc(uint32_t smem_addr) {
    return ((uint64_t)2 << 61) | ((uint64_t)1 << 46) | ((uint64_t)64 << 32) |
           ((uint64_t)1 << 16) | (((uint64_t)(smem_addr >> 4)) & 0x3FFF);
}
__device__ __forceinline__ void ldtm_x32(uint32_t* r, uint32_t tmem) {
    asm volatile(
        "tcgen05.ld.sync.aligned.32x32b.x32.b32 "
        "{%0,%1,%2,%3,%4,%5,%6,%7,%8,%9,%10,%11,%12,%13,%14,%15,"
        "%16,%17,%18,%19,%20,%21,%22,%23,%24,%25,%26,%27,%28,%29,%30,%31}, [%32];"
        : "=r"(r[0]),"=r"(r[1]),"=r"(r[2]),"=r"(r[3]),"=r"(r[4]),"=r"(r[5]),"=r"(r[6]),"=r"(r[7]),
          "=r"(r[8]),"=r"(r[9]),"=r"(r[10]),"=r"(r[11]),"=r"(r[12]),"=r"(r[13]),"=r"(r[14]),"=r"(r[15]),
          "=r"(r[16]),"=r"(r[17]),"=r"(r[18]),"=r"(r[19]),"=r"(r[20]),"=r"(r[21]),"=r"(r[22]),"=r"(r[23]),
          "=r"(r[24]),"=r"(r[25]),"=r"(r[26]),"=r"(r[27]),"=r"(r[28]),"=r"(r[29]),"=r"(r[30]),"=r"(r[31])
        : "r"(tmem));
}
#endif  // TC_LIVE

__global__ __launch_bounds__(256, 1)
void gemm_tc_kernel(float* __restrict__ Out) {
#ifdef TC_LIVE
    if (threadIdx.x == 0) g_done = 1;

    extern __shared__ char smem_raw[];
    char* smem = (char*)(((uintptr_t)smem_raw + 1023) & ~(uintptr_t)1023);
    const uint32_t sbase = (uint32_t)__cvta_generic_to_shared(smem);
    const uint32_t mbarb = sbase + SMEM_STAGES;  // +0,8,16: stage mbars; +24: final; +32: tmem ptr

    const int tid  = threadIdx.x;
    const int wid  = tid >> 5;
    const int lane = tid & 31;
    const int bm = blockIdx.x * BM;
    const int bn = blockIdx.y * BN;

    if (tid == 0) {
#pragma unroll
        for (int i = 0; i < 4; i++) mbar_init(mbarb + 8 * i, 1);
    }
    if (wid == 0) {
        asm volatile("tcgen05.alloc.cta_group::1.sync.aligned.shared::cta.b32 [%0], %1;"
                     :: "r"(mbarb + 32), "r"(512) : "memory");
        asm volatile("tcgen05.relinquish_alloc_permit.cta_group::1.sync.aligned;");
    }
    __syncthreads();
    uint32_t tmem;
    asm volatile("ld.shared.b32 %0, [%1];" : "=r"(tmem) : "r"(mbarb + 32));

    // Load one K-chunk (A: 256x64, B: 256x64) into stage s. 16 cp.async/thread.
    auto load_chunk = [&](int kt, int s) {
        uint32_t a_s = sbase + s * STAGE_BYTES;
        uint32_t b_s = a_s + STAGE_A_BYTES;
        const __half* Ag = g_X  + (size_t)bm * K_DIM + kt * BK;
        const __half* Bg = g_Wt + (size_t)bn * K_DIM + kt * BK;
#pragma unroll
        for (int i = 0; i < 8; i++) {
            int idx = tid + 256 * i;                 // 0..2047
            int row = idx >> 3, c16 = idx & 7;
            cp_async16(a_s + row * 128 + ((c16 ^ (row & 7)) << 4),
                       Ag + (size_t)row * K_DIM + c16 * 8);
        }
#pragma unroll
        for (int i = 0; i < 8; i++) {
            int idx = tid + 256 * i;
            int row = idx >> 3, c16 = idx & 7;
            cp_async16(b_s + row * 128 + ((c16 ^ (row & 7)) << 4),
                       Bg + (size_t)row * K_DIM + c16 * 8);
        }
    };

    const uint32_t idesc = (8u << 24) | (16u << 17) | (1u << 4);  // M=128, N=128, f16->f32
    const int KT = K_DIM / BK;  // 64

    // Prefetch 2 chunks (stages 0,1)
    load_chunk(0, 0);
    asm volatile("cp.async.commit_group;" ::: "memory");
    load_chunk(1, 1);
    asm volatile("cp.async.commit_group;" ::: "memory");

    for (int kt = 0; kt < KT; kt++) {
        const int s = kt % 3;
        // chunk kt resident (leave 1 newer group in flight)
        asm volatile("cp.async.wait_group 1;" ::: "memory");
        __syncthreads();

        // Issue MMAs for chunk kt (async), then refill the oldest stage.
        if (wid == 0) {
            asm volatile("fence.proxy.async.shared::cta;" ::: "memory");
            if (elect_one()) {
                uint32_t a_s = sbase + s * STAGE_BYTES;
                uint32_t b_s = a_s + STAGE_A_BYTES;
                uint64_t ad0 = make_desc(a_s);
                uint64_t ad1 = make_desc(a_s + 16384);
                uint64_t bd0 = make_desc(b_s);
                uint64_t bd1 = make_desc(b_s + 16384);
#pragma unroll
                for (int ks = 0; ks < 4; ks++) {
                    uint32_t en = (kt > 0 || ks > 0) ? 1u : 0u;
                    mma_f16_ss(tmem,       ad0 + ks * 2, bd0 + ks * 2, idesc, en);
                    mma_f16_ss(tmem + 128, ad0 + ks * 2, bd1 + ks * 2, idesc, en);
                    mma_f16_ss(tmem + 256, ad1 + ks * 2, bd0 + ks * 2, idesc, en);
                    mma_f16_ss(tmem + 384, ad1 + ks * 2, bd1 + ks * 2, idesc, en);
                }
                tc_commit(mbarb + 8 * s);
            }
        }

        // Refill stage (kt+2)%3 (currently holds chunk kt-1): wait its MMA first.
        if (kt + 2 < KT) {
            if (kt >= 1)
                mbar_wait(mbarb + 8 * ((kt + 2) % 3), ((kt - 1) / 3) & 1);
            load_chunk(kt + 2, (kt + 2) % 3);
        }
        asm volatile("cp.async.commit_group;" ::: "memory");
    }

    // Final completion barrier for all MMAs
    if (wid == 0 && elect_one()) tc_commit(mbarb + 24);
    mbar_wait(mbarb + 24, 0);
    asm volatile("tcgen05.fence::after_thread_sync;" ::: "memory");

    // Epilogue: warp w -> M-half (w>>2), rows (w&3)*32; 256 cols each.
    {
        const int h   = wid >> 2;
        const int row = bm + h * 128 + (wid & 3) * 32 + lane;
        float* dst = Out + (size_t)row * N_DIM + bn;
        const uint32_t tm = tmem + h * 256;
#pragma unroll
        for (int b = 0; b < 8; b++) {
            uint32_t v[32];
            ldtm_x32(v, tm + b * 32);
            asm volatile("tcgen05.wait::ld.sync.aligned;" ::: "memory");
#pragma unroll
            for (int i = 0; i < 8; i++) {
                float4 f;
                f.x = __uint_as_float(v[4 * i + 0]);
                f.y = __uint_as_float(v[4 * i + 1]);
                f.z = __uint_as_float(v[4 * i + 2]);
                f.w = __uint_as_float(v[4 * i + 3]);
                *reinterpret_cast<float4*>(dst + b * 32 + i * 4) = f;
            }
        }
    }
    __syncthreads();
    if (wid == 0) {
        asm volatile("tcgen05.dealloc.cta_group::1.sync.aligned.b32 %0, %1;"
                     :: "r"(tmem), "r"(512));
    }
#endif  // TC_LIVE
}

// ---------------------------------------------------------------------------
// Fallback GEMM (mma.sync). Runs only if tcgen05 path was stubbed out.
// ---------------------------------------------------------------------------
__global__ __launch_bounds__(256, 2)
void gemm_fb_kernel(float* __restrict__ Out) {
    if (*(volatile int*)&g_done) return;

    extern __shared__ __half fsm[];
    __half (*As)[128][FB_STRIDE] = (__half(*)[128][FB_STRIDE])fsm;
    __half (*Bs)[128][FB_STRIDE] = (__half(*)[128][FB_STRIDE])(fsm + 3 * FB_STAGE_HALFS);

    const int tid  = threadIdx.x;
    const int warp = tid >> 5;
    const int lane = tid & 31;
    const int wm = (warp & 1) * 64;
    const int wn = (warp >> 1) * 32;
    const int bm = blockIdx.y * 128;
    const int bn = blockIdx.x * 128;

    float acc[4][4][4];
#pragma unroll
    for (int i = 0; i < 4; i++)
#pragma unroll
        for (int j = 0; j < 4; j++)
#pragma unroll
            for (int r = 0; r < 4; r++) acc[i][j][r] = 0.f;

    const int l_row = tid >> 2;
    const int l_col = (tid & 3) * 8;

    auto load = [&](int kt, int s) {
        const int k0 = kt * 32;
#pragma unroll
        for (int it = 0; it < 2; it++) {
            int r = l_row + it * 64;
            cp_async16((uint32_t)__cvta_generic_to_shared(&As[s][r][l_col]),
                       g_X + (size_t)(bm + r) * K_DIM + k0 + l_col);
        }
#pragma unroll
        for (int it = 0; it < 2; it++) {
            int r = l_row + it * 64;
            cp_async16((uint32_t)__cvta_generic_to_shared(&Bs[s][r][l_col]),
                       g_Wt + (size_t)(bn + r) * K_DIM + k0 + l_col);
        }
    };

    const int KT = K_DIM / 32;
    load(0, 0);
    asm volatile("cp.async.commit_group;" ::: "memory");
    load(1, 1);
    asm volatile("cp.async.commit_group;" ::: "memory");

    for (int kt = 0; kt < KT; kt++) {
        const int s = kt % 3;
        asm volatile("cp.async.wait_group 1;" ::: "memory");
        __syncthreads();
        if (kt + 2 < KT) load(kt + 2, (kt + 2) % 3);
        asm volatile("cp.async.commit_group;" ::: "memory");

#pragma unroll
        for (int kk = 0; kk < 2; kk++) {
            uint32_t a[4][4];
#pragma unroll
            for (int i = 0; i < 4; i++) {
                uint32_t addr = (uint32_t)__cvta_generic_to_shared(
                    &As[s][wm + i * 16 + (lane & 15)][kk * 16 + ((lane >> 4) << 3)]);
                asm volatile(
                    "ldmatrix.sync.aligned.m8n8.x4.shared.b16 {%0,%1,%2,%3}, [%4];\n"
                    : "=r"(a[i][0]), "=r"(a[i][1]), "=r"(a[i][2]), "=r"(a[i][3])
                    : "r"(addr));
            }
            uint32_t b[4][2];
#pragma unroll
            for (int jj = 0; jj < 2; jj++) {
                int grp = lane >> 3;
                uint32_t addr = (uint32_t)__cvta_generic_to_shared(
                    &Bs[s][wn + jj * 16 + (grp >> 1) * 8 + (lane & 7)]
                         [kk * 16 + (grp & 1) * 8]);
                uint32_t r0, r1, r2, r3;
                asm volatile(
                    "ldmatrix.sync.aligned.m8n8.x4.shared.b16 {%0,%1,%2,%3}, [%4];\n"
                    : "=r"(r0), "=r"(r1), "=r"(r2), "=r"(r3)
                    : "r"(addr));
                b[jj * 2][0] = r0;     b[jj * 2][1] = r1;
                b[jj * 2 + 1][0] = r2; b[jj * 2 + 1][1] = r3;
            }
#pragma unroll
            for (int i = 0; i < 4; i++)
#pragma unroll
                for (int j = 0; j < 4; j++) {
                    asm volatile(
                        "mma.sync.aligned.m16n8k16.row.col.f32.f16.f16.f32 "
                        "{%0,%1,%2,%3}, {%4,%5,%6,%7}, {%8,%9}, {%0,%1,%2,%3};\n"
                        : "+f"(acc[i][j][0]), "+f"(acc[i][j][1]),
                          "+f"(acc[i][j][2]), "+f"(acc[i][j][3])
                        : "r"(a[i][0]), "r"(a[i][1]), "r"(a[i][2]), "r"(a[i][3]),
                          "r"(b[j][0]), "r"(b[j][1]));
                }
        }
    }

#pragma unroll
    for (int i = 0; i < 4; i++) {
        int row = bm + wm + i * 16 + (lane >> 2);
#pragma unroll
        for (int j = 0; j < 4; j++) {
            int col = bn + wn + j * 8 + (lane & 3) * 2;
            *reinterpret_cast<float2*>(&Out[(size_t)row * N_DIM + col]) =
                make_float2(acc[i][j][0], acc[i][j][1]);
            *reinterpret_cast<float2*>(&Out[(size_t)(row + 8) * N_DIM + col]) =
                make_float2(acc[i][j][2], acc[i][j][3]);
        }
    }
}

// ---------------------------------------------------------------------------
extern "C" void kernel_launch(void* const* d_in, const int* in_sizes, int n_in,
                              void* d_out, int out_size) {
    const float* x  = (const float*)d_in[0];
    const int*   qw = (const int*)d_in[1];
    const int*   qz = (const int*)d_in[2];
    const float* sc = (const float*)d_in[3];
    float* out = (float*)d_out;

    cudaFuncSetAttribute(gemm_tc_kernel, cudaFuncAttributeMaxDynamicSharedMemorySize,
                         SMEM_TOTAL);
    cudaFuncSetAttribute(gemm_fb_kernel, cudaFuncAttributeMaxDynamicSharedMemorySize,
                         FB_SMEM_BYTES);

    reset_flag_kernel<<<1, 1>>>();

    const int x_total = in_sizes[0];
    convert_x_kernel<<<(x_total / 4 + 255) / 256, 256>>>(x, x_total);

    dim3 dq_grid(K_DIM / 64, N_DIM / 256);
    dequant_t_kernel<<<dq_grid, 256>>>(qw, qz, sc);

    dim3 tc_grid(M_DIM / BM, N_DIM / BN);       // (32, 43)
    gemm_tc_kernel<<<tc_grid, 256, SMEM_TOTAL>>>(out);

    dim3 fb_grid(N_DIM / 128, M_DIM / 128);
    gemm_fb_kernel<<<fb_grid, 256, FB_SMEM_BYTES>>>(out);
}

// round 6
// speedup vs baseline: 3.1947x; 1.1445x over previous
#include <cuda_runtime.h>
#include <cuda_fp16.h>
#include <cstdint>

// Problem constants
#define M_DIM 8192
#define K_DIM 4096
#define N_DIM 11008
#define NP    (N_DIM / 8)

// tcgen05 GEMM tiling: CTA tile 256x256, BK=64, 3 stages, warp-specialized
#define BM 256
#define BN 256
#define BK 64
#define STAGE_A_BYTES (BM * BK * 2)                     // 32768
#define STAGE_B_BYTES (BN * BK * 2)                     // 32768
#define STAGE_BYTES   (STAGE_A_BYTES + STAGE_B_BYTES)   // 65536
#define NSTAGES 3
#define SMEM_STAGES   (NSTAGES * STAGE_BYTES)           // 196608
#define SMEM_TOTAL    (SMEM_STAGES + 1024 + 128)

// Fallback GEMM tiling (mma.sync): 128x128x32, 3 stages
#define FB_STRIDE 40
#define FB_STAGE_HALFS (128 * FB_STRIDE)
#define FB_SMEM_BYTES (3 * 2 * FB_STAGE_HALFS * 2)      // 61440

// Static device scratch
__device__ __half g_Wt[(size_t)N_DIM * K_DIM];  // W transposed [N][K], fp16
__device__ __half g_X [(size_t)M_DIM * K_DIM];  // activations fp16
__device__ int    g_done;

// ---------------------------------------------------------------------------
__device__ __forceinline__ void cp_async16(uint32_t smem, const void* gmem) {
    asm volatile("cp.async.cg.shared.global [%0], [%1], 16;\n"
                 :: "r"(smem), "l"(gmem) : "memory");
}

__global__ void reset_flag_kernel() { g_done = 0; }

// ---------------------------------------------------------------------------
// Pass 0: x fp32 -> fp16 (lossless)
// ---------------------------------------------------------------------------
__global__ void convert_x_kernel(const float* __restrict__ x, int total) {
    int i = (blockIdx.x * blockDim.x + threadIdx.x) * 4;
    if (i >= total) return;
    float4 v = *reinterpret_cast<const float4*>(x + i);
    __half h[4];
    h[0] = __float2half(v.x); h[1] = __float2half(v.y);
    h[2] = __float2half(v.z); h[3] = __float2half(v.w);
    *reinterpret_cast<uint2*>(&g_X[i]) = *reinterpret_cast<uint2*>(h);
}

// ---------------------------------------------------------------------------
// Pass 1: dequant AWQ int4 -> fp16 transposed g_Wt[n][k] (smem transpose)
// ---------------------------------------------------------------------------
__global__ __launch_bounds__(256)
void dequant_t_kernel(const int* __restrict__ qweight,
                      const int* __restrict__ qzeros,
                      const float* __restrict__ scales) {
    __shared__ __half s[256][64];
    const int k0 = blockIdx.x * 64;
    const int n0 = blockIdx.y * 256;
    const int g  = k0 >> 7;
    const int c0 = n0 >> 3;
    const int tid = threadIdx.x;

#pragma unroll
    for (int i = 0; i < 8; i++) {
        int lin = tid + 256 * i;
        int cl  = lin & 31;
        int kl  = lin >> 5;
        uint32_t w = (uint32_t)qweight[(size_t)(k0 + kl) * NP + c0 + cl];
        uint32_t z = (uint32_t)qzeros[(size_t)g * NP + c0 + cl];
        const float* sp = scales + (size_t)g * N_DIM + n0 + cl * 8;
#pragma unroll
        for (int j = 0; j < 8; j++) {
            float wi = (float)((w >> (4 * j)) & 15u);
            float zi = (float)((z >> (4 * j)) & 15u);
            __half v = __float2half((wi - zi) * sp[j]);
            int nl = cl * 8 + j;
            int phys16 = (kl >> 3) ^ ((nl >> 3) & 7);
            s[nl][(phys16 << 3) | (kl & 7)] = v;
        }
    }
    __syncthreads();
#pragma unroll
    for (int i = 0; i < 8; i++) {
        int idx = tid + 256 * i;
        int r = idx >> 3, q = idx & 7;
        int phys16 = q ^ ((r >> 3) & 7);
        uint4 v = *reinterpret_cast<uint4*>(&s[r][phys16 << 3]);
        *reinterpret_cast<uint4*>(&g_Wt[(size_t)(n0 + r) * K_DIM + k0 + q * 8]) = v;
    }
}

// ---------------------------------------------------------------------------
// tcgen05 GEMM (device pass must target sm_103a / sm_100a family)
// ---------------------------------------------------------------------------
#if defined(__CUDA_ARCH__) && (defined(__CUDA_ARCH_FEAT_SM103_ALL) || defined(__CUDA_ARCH_FEAT_SM100_ALL) || defined(__CUDA_ARCH_FEAT_SM101_ALL))
#define TC_LIVE 1
#endif

#ifdef TC_LIVE
__device__ __forceinline__ uint32_t elect_one() {
    uint32_t p;
    asm volatile("{\n\t.reg .pred P;\n\telect.sync _|P, 0xFFFFFFFF;\n\t"
                 "selp.b32 %0, 1, 0, P;\n\t}" : "=r"(p));
    return p;
}
__device__ __forceinline__ void mbar_init(uint32_t a, uint32_t cnt) {
    asm volatile("mbarrier.init.shared.b64 [%0], %1;" :: "r"(a), "r"(cnt) : "memory");
}
__device__ __forceinline__ void mbar_wait(uint32_t a, uint32_t parity) {
    asm volatile("{\n\t.reg .pred P;\n\tLW%=:\n\t"
                 "mbarrier.try_wait.parity.acquire.cta.shared::cta.b64 P, [%0], %1;\n\t"
                 "@!P bra LW%=;\n\t}" :: "r"(a), "r"(parity) : "memory");
}
__device__ __forceinline__ void cpasync_arrive_noinc(uint32_t a) {
    asm volatile("cp.async.mbarrier.arrive.noinc.shared.b64 [%0];"
                 :: "r"(a) : "memory");
}
__device__ __forceinline__ void tc_commit(uint32_t mbar) {
    asm volatile("tcgen05.commit.cta_group::1.mbarrier::arrive::one.shared::cluster.b64 [%0];"
                 :: "r"(mbar) : "memory");
}
__device__ __forceinline__ void mma_f16_ss(uint32_t d, uint64_t ad, uint64_t bd,
                                           uint32_t idesc, uint32_t en) {
    asm volatile("{\n\t.reg .pred p;\n\tsetp.ne.u32 p, %4, 0;\n\t"
                 "tcgen05.mma.cta_group::1.kind::f16 [%0], %1, %2, %3, {%5,%5,%5,%5}, p;\n\t}"
                 :: "r"(d), "l"(ad), "l"(bd), "r"(idesc), "r"(en), "r"(0u) : "memory");
}
__device__ __forceinline__ uint64_t make_desc(uint32_t smem_addr) {
    return ((uint64_t)2 << 61) | ((uint64_t)1 << 46) | ((uint64_t)64 << 32) |
           ((uint64_t)1 << 16) | (((uint64_t)(smem_addr >> 4)) & 0x3FFF);
}
__device__ __forceinline__ void ldtm_x32(uint32_t* r, uint32_t tmem) {
    asm volatile(
        "tcgen05.ld.sync.aligned.32x32b.x32.b32 "
        "{%0,%1,%2,%3,%4,%5,%6,%7,%8,%9,%10,%11,%12,%13,%14,%15,"
        "%16,%17,%18,%19,%20,%21,%22,%23,%24,%25,%26,%27,%28,%29,%30,%31}, [%32];"
        : "=r"(r[0]),"=r"(r[1]),"=r"(r[2]),"=r"(r[3]),"=r"(r[4]),"=r"(r[5]),"=r"(r[6]),"=r"(r[7]),
          "=r"(r[8]),"=r"(r[9]),"=r"(r[10]),"=r"(r[11]),"=r"(r[12]),"=r"(r[13]),"=r"(r[14]),"=r"(r[15]),
          "=r"(r[16]),"=r"(r[17]),"=r"(r[18]),"=r"(r[19]),"=r"(r[20]),"=r"(r[21]),"=r"(r[22]),"=r"(r[23]),
          "=r"(r[24]),"=r"(r[25]),"=r"(r[26]),"=r"(r[27]),"=r"(r[28]),"=r"(r[29]),"=r"(r[30]),"=r"(r[31])
        : "r"(tmem));
}
#endif  // TC_LIVE

// 288 threads: warps 0-7 = producers (cp.async), warp 8 = MMA issuer.
__global__ __launch_bounds__(288, 1)
void gemm_tc_kernel(float* __restrict__ Out) {
#ifdef TC_LIVE
    if (threadIdx.x == 0) g_done = 1;

    extern __shared__ char smem_raw[];
    char* smem = (char*)(((uintptr_t)smem_raw + 1023) & ~(uintptr_t)1023);
    const uint32_t sbase = (uint32_t)__cvta_generic_to_shared(smem);
    const uint32_t mbarb = sbase + SMEM_STAGES;
    // full[s]: +0,+8,+16 ; empty[s]: +24,+32,+40 ; fin: +48 ; tmem ptr: +56

    const int tid  = threadIdx.x;
    const int wid  = tid >> 5;
    const int lane = tid & 31;
    const int bm = blockIdx.x * BM;
    const int bn = blockIdx.y * BN;

    if (tid == 0) {
#pragma unroll
        for (int s = 0; s < 3; s++) {
            mbar_init(mbarb + 8 * s, 256);       // full: 256 producer arrivals
            mbar_init(mbarb + 24 + 8 * s, 1);    // empty: 1 commit arrival
        }
        mbar_init(mbarb + 48, 1);                // fin
    }
    if (wid == 8) {
        asm volatile("tcgen05.alloc.cta_group::1.sync.aligned.shared::cta.b32 [%0], %1;"
                     :: "r"(mbarb + 56), "r"(512) : "memory");
        asm volatile("tcgen05.relinquish_alloc_permit.cta_group::1.sync.aligned;");
    }
    __syncthreads();
    uint32_t tmem;
    asm volatile("ld.shared.b32 %0, [%1];" : "=r"(tmem) : "r"(mbarb + 56));

    const int KT = K_DIM / BK;  // 64

    if (wid < 8) {
        // ------------------ producer warps (256 threads) -------------------
        for (int kt = 0; kt < KT; kt++) {
            const int s = kt % 3;
            const uint32_t e_par = ((kt / 3) & 1) ^ 1;   // first 3 uses pass
            mbar_wait(mbarb + 24 + 8 * s, e_par);

            uint32_t a_s = sbase + s * STAGE_BYTES;
            uint32_t b_s = a_s + STAGE_A_BYTES;
            const __half* Ag = g_X  + (size_t)bm * K_DIM + kt * BK;
            const __half* Bg = g_Wt + (size_t)bn * K_DIM + kt * BK;
#pragma unroll
            for (int i = 0; i < 8; i++) {
                int idx = tid + 256 * i;                 // 0..2047
                int row = idx >> 3, c16 = idx & 7;
                cp_async16(a_s + row * 128 + ((c16 ^ (row & 7)) << 4),
                           Ag + (size_t)row * K_DIM + c16 * 8);
            }
#pragma unroll
            for (int i = 0; i < 8; i++) {
                int idx = tid + 256 * i;
                int row = idx >> 3, c16 = idx & 7;
                cp_async16(b_s + row * 128 + ((c16 ^ (row & 7)) << 4),
                           Bg + (size_t)row * K_DIM + c16 * 8);
            }
            cpasync_arrive_noinc(mbarb + 8 * s);
        }
    } else if (elect_one()) {
        // ------------------ MMA issuer (1 thread of warp 8) ----------------
        const uint32_t idesc = (8u << 24) | (16u << 17) | (1u << 4);
        for (int kt = 0; kt < KT; kt++) {
            const int s = kt % 3;
            mbar_wait(mbarb + 8 * s, (kt / 3) & 1);
            asm volatile("fence.proxy.async.shared::cta;" ::: "memory");

            uint32_t a_s = sbase + s * STAGE_BYTES;
            uint32_t b_s = a_s + STAGE_A_BYTES;
            uint64_t ad0 = make_desc(a_s);
            uint64_t ad1 = make_desc(a_s + 16384);
            uint64_t bd0 = make_desc(b_s);
            uint64_t bd1 = make_desc(b_s + 16384);
#pragma unroll
            for (int ks = 0; ks < 4; ks++) {
                uint32_t en = (kt > 0 || ks > 0) ? 1u : 0u;
                mma_f16_ss(tmem,       ad0 + ks * 2, bd0 + ks * 2, idesc, en);
                mma_f16_ss(tmem + 128, ad0 + ks * 2, bd1 + ks * 2, idesc, en);
                mma_f16_ss(tmem + 256, ad1 + ks * 2, bd0 + ks * 2, idesc, en);
                mma_f16_ss(tmem + 384, ad1 + ks * 2, bd1 + ks * 2, idesc, en);
            }
            tc_commit(mbarb + 24 + 8 * s);   // recycle stage on MMA completion
        }
        tc_commit(mbarb + 48);
    }

    // All 288 threads: wait for all MMAs to drain
    mbar_wait(mbarb + 48, 0);
    asm volatile("tcgen05.fence::after_thread_sync;" ::: "memory");

    // Epilogue (warps 0-7): warp w -> M-half (w>>2), rows (w&3)*32
    if (wid < 8) {
        const int h   = wid >> 2;
        const int row = bm + h * 128 + (wid & 3) * 32 + lane;
        float* dst = Out + (size_t)row * N_DIM + bn;
        const uint32_t tm = tmem + h * 256;
#pragma unroll
        for (int b = 0; b < 8; b++) {
            uint32_t v[32];
            ldtm_x32(v, tm + b * 32);
            asm volatile("tcgen05.wait::ld.sync.aligned;" ::: "memory");
#pragma unroll
            for (int i = 0; i < 8; i++) {
                float4 f;
                f.x = __uint_as_float(v[4 * i + 0]);
                f.y = __uint_as_float(v[4 * i + 1]);
                f.z = __uint_as_float(v[4 * i + 2]);
                f.w = __uint_as_float(v[4 * i + 3]);
                *reinterpret_cast<float4*>(dst + b * 32 + i * 4) = f;
            }
        }
    }
    __syncthreads();
    if (wid == 8) {
        asm volatile("tcgen05.dealloc.cta_group::1.sync.aligned.b32 %0, %1;"
                     :: "r"(tmem), "r"(512));
    }
#endif  // TC_LIVE
}

// ---------------------------------------------------------------------------
// Fallback GEMM (mma.sync). Runs only if tcgen05 path was stubbed out.
// ---------------------------------------------------------------------------
__global__ __launch_bounds__(256, 2)
void gemm_fb_kernel(float* __restrict__ Out) {
    if (*(volatile int*)&g_done) return;

    extern __shared__ __half fsm[];
    __half (*As)[128][FB_STRIDE] = (__half(*)[128][FB_STRIDE])fsm;
    __half (*Bs)[128][FB_STRIDE] = (__half(*)[128][FB_STRIDE])(fsm + 3 * FB_STAGE_HALFS);

    const int tid  = threadIdx.x;
    const int warp = tid >> 5;
    const int lane = tid & 31;
    const int wm = (warp & 1) * 64;
    const int wn = (warp >> 1) * 32;
    const int bm = blockIdx.y * 128;
    const int bn = blockIdx.x * 128;

    float acc[4][4][4];
#pragma unroll
    for (int i = 0; i < 4; i++)
#pragma unroll
        for (int j = 0; j < 4; j++)
#pragma unroll
            for (int r = 0; r < 4; r++) acc[i][j][r] = 0.f;

    const int l_row = tid >> 2;
    const int l_col = (tid & 3) * 8;

    auto load = [&](int kt, int s) {
        const int k0 = kt * 32;
#pragma unroll
        for (int it = 0; it < 2; it++) {
            int r = l_row + it * 64;
            cp_async16((uint32_t)__cvta_generic_to_shared(&As[s][r][l_col]),
                       g_X + (size_t)(bm + r) * K_DIM + k0 + l_col);
        }
#pragma unroll
        for (int it = 0; it < 2; it++) {
            int r = l_row + it * 64;
            cp_async16((uint32_t)__cvta_generic_to_shared(&Bs[s][r][l_col]),
                       g_Wt + (size_t)(bn + r) * K_DIM + k0 + l_col);
        }
    };

    const int KT = K_DIM / 32;
    load(0, 0);
    asm volatile("cp.async.commit_group;" ::: "memory");
    load(1, 1);
    asm volatile("cp.async.commit_group;" ::: "memory");

    for (int kt = 0; kt < KT; kt++) {
        const int s = kt % 3;
        asm volatile("cp.async.wait_group 1;" ::: "memory");
        __syncthreads();
        if (kt + 2 < KT) load(kt + 2, (kt + 2) % 3);
        asm volatile("cp.async.commit_group;" ::: "memory");

#pragma unroll
        for (int kk = 0; kk < 2; kk++) {
            uint32_t a[4][4];
#pragma unroll
            for (int i = 0; i < 4; i++) {
                uint32_t addr = (uint32_t)__cvta_generic_to_shared(
                    &As[s][wm + i * 16 + (lane & 15)][kk * 16 + ((lane >> 4) << 3)]);
                asm volatile(
                    "ldmatrix.sync.aligned.m8n8.x4.shared.b16 {%0,%1,%2,%3}, [%4];\n"
                    : "=r"(a[i][0]), "=r"(a[i][1]), "=r"(a[i][2]), "=r"(a[i][3])
                    : "r"(addr));
            }
            uint32_t b[4][2];
#pragma unroll
            for (int jj = 0; jj < 2; jj++) {
                int grp = lane >> 3;
                uint32_t addr = (uint32_t)__cvta_generic_to_shared(
                    &Bs[s][wn + jj * 16 + (grp >> 1) * 8 + (lane & 7)]
                         [kk * 16 + (grp & 1) * 8]);
                uint32_t r0, r1, r2, r3;
                asm volatile(
                    "ldmatrix.sync.aligned.m8n8.x4.shared.b16 {%0,%1,%2,%3}, [%4];\n"
                    : "=r"(r0), "=r"(r1), "=r"(r2), "=r"(r3)
                    : "r"(addr));
                b[jj * 2][0] = r0;     b[jj * 2][1] = r1;
                b[jj * 2 + 1][0] = r2; b[jj * 2 + 1][1] = r3;
            }
#pragma unroll
            for (int i = 0; i < 4; i++)
#pragma unroll
                for (int j = 0; j < 4; j++) {
                    asm volatile(
                        "mma.sync.aligned.m16n8k16.row.col.f32.f16.f16.f32 "
                        "{%0,%1,%2,%3}, {%4,%5,%6,%7}, {%8,%9}, {%0,%1,%2,%3};\n"
                        : "+f"(acc[i][j][0]), "+f"(acc[i][j][1]),
                          "+f"(acc[i][j][2]), "+f"(acc[i][j][3])
                        : "r"(a[i][0]), "r"(a[i][1]), "r"(a[i][2]), "r"(a[i][3]),
                          "r"(b[j][0]), "r"(b[j][1]));
                }
        }
    }

#pragma unroll
    for (int i = 0; i < 4; i++) {
        int row = bm + wm + i * 16 + (lane >> 2);
#pragma unroll
        for (int j = 0; j < 4; j++) {
            int col = bn + wn + j * 8 + (lane & 3) * 2;
            *reinterpret_cast<float2*>(&Out[(size_t)row * N_DIM + col]) =
                make_float2(acc[i][j][0], acc[i][j][1]);
            *reinterpret_cast<float2*>(&Out[(size_t)(row + 8) * N_DIM + col]) =
                make_float2(acc[i][j][2], acc[i][j][3]);
        }
    }
}

// ---------------------------------------------------------------------------
extern "C" void kernel_launch(void* const* d_in, const int* in_sizes, int n_in,
                              void* d_out, int out_size) {
    const float* x  = (const float*)d_in[0];
    const int*   qw = (const int*)d_in[1];
    const int*   qz = (const int*)d_in[2];
    const float* sc = (const float*)d_in[3];
    float* out = (float*)d_out;

    cudaFuncSetAttribute(gemm_tc_kernel, cudaFuncAttributeMaxDynamicSharedMemorySize,
                         SMEM_TOTAL);
    cudaFuncSetAttribute(gemm_fb_kernel, cudaFuncAttributeMaxDynamicSharedMemorySize,
                         FB_SMEM_BYTES);

    reset_flag_kernel<<<1, 1>>>();

    const int x_total = in_sizes[0];
    convert_x_kernel<<<(x_total / 4 + 255) / 256, 256>>>(x, x_total);

    dim3 dq_grid(K_DIM / 64, N_DIM / 256);
    dequant_t_kernel<<<dq_grid, 256>>>(qw, qz, sc);

    dim3 tc_grid(M_DIM / BM, N_DIM / BN);       // (32, 43)
    gemm_tc_kernel<<<tc_grid, 288, SMEM_TOTAL>>>(out);

    dim3 fb_grid(N_DIM / 128, M_DIM / 128);
    gemm_fb_kernel<<<fb_grid, 256, FB_SMEM_BYTES>>>(out);
}